// round 2
// baseline (speedup 1.0000x reference)
#include <cuda_runtime.h>
#include <math.h>

// ---------------- problem constants ----------------
#define N8   130560   // (2176/8)*(3840/8)
#define N16  32640    // (2176/16)*(3840/16)
#define N32  8160     // (2176/32)*(3840/32)
#define NT   (N8 + N16 + N32)   // 171360
#define FW8  480
#define FW16 240
#define FW32 120
#define TOPK 1000
#define NCAND 4096
#define NBINS 4096
#define NMS_T 0.4f

// ---------------- device scratch (no allocations allowed) ----------------
__device__ unsigned int        g_keys[NT];
__device__ unsigned int        g_hist[NBINS];
__device__ unsigned int        g_keymin;
__device__ unsigned int        g_ccount;
__device__ unsigned long long  g_cand[NCAND];
__device__ unsigned int        g_sel_key[1024];
__device__ unsigned int        g_sel_idx[1024];
__device__ float               g_bx[TOPK * 4];
__device__ float               g_sc[TOPK];
__device__ float               g_kp[TOPK * 10];
__device__ int                 g_val[TOPK];

// ---------------- K0: zero scratch (must run every graph replay) ----------------
__global__ void k_zero() {
    int i = blockIdx.x * blockDim.x + threadIdx.x;
    if (i < NBINS) g_hist[i] = 0;
    if (i == 0) g_ccount = 0;
}

// ---------------- K1: sigmoid -> key + histogram ----------------
// valid (sigmoid > 0.5) keys are in (0x3F000000, 0x3F800000]; bin = mantissa[22:11]
__global__ void k_keys(const float* __restrict__ s8,
                       const float* __restrict__ s16,
                       const float* __restrict__ s32) {
    int i = blockIdx.x * blockDim.x + threadIdx.x;
    if (i >= NT) return;
    float raw;
    if (i < N8)            raw = s8[i];
    else if (i < N8 + N16) raw = s16[i - N8];
    else                   raw = s32[i - N8 - N16];
    float sg = 1.0f / (1.0f + expf(-raw));
    unsigned int key = 0u;
    if (sg > 0.5f) key = __float_as_uint(sg);
    g_keys[i] = key;
    if (key) {
        unsigned int off = key - 0x3F000000u;        // in [1, 0x800000]
        unsigned int bin = off >> 11;
        if (bin > NBINS - 1) bin = NBINS - 1;
        atomicAdd(&g_hist[bin], 1u);
    }
}

// ---------------- K2: find key threshold so candidate count >= TOPK ----------------
__global__ void k_select() {
    __shared__ unsigned int sh[NBINS];
    __shared__ unsigned int a[1024];
    int t = threadIdx.x;

    for (int i = t; i < NBINS; i += 1024) sh[i] = g_hist[i];
    __syncthreads();

    // per-thread partial over 4 bins
    unsigned int p = sh[t * 4] + sh[t * 4 + 1] + sh[t * 4 + 2] + sh[t * 4 + 3];
    a[t] = p;
    __syncthreads();

    // Hillis-Steele suffix sum: a[t] = sum of partials t..1023
    for (int d = 1; d < 1024; d <<= 1) {
        unsigned int v = a[t] + ((t + d < 1024) ? a[t + d] : 0u);
        __syncthreads();
        a[t] = v;
        __syncthreads();
    }

    unsigned int nxt = (t < 1023) ? a[t + 1] : 0u;
    // unique boundary group: suffix >= TOPK here, < TOPK after
    if (a[t] >= TOPK && nxt < TOPK) {
        unsigned int running = nxt;
        int B = t * 4;
        for (int b = t * 4 + 3; b >= t * 4; b--) {
            running += sh[b];
            if (running >= TOPK) { B = b; break; }
        }
        g_keymin = 0x3F000000u + ((unsigned int)B << 11);
    }
    if (t == 0 && a[0] < TOPK) {
        // fewer than TOPK valid: collect all valid
        g_keymin = 0x3F000000u;
    }
}

// ---------------- K3: collect candidates ----------------
__global__ void k_collect() {
    int i = blockIdx.x * blockDim.x + threadIdx.x;
    if (i >= NT) return;
    unsigned int key = g_keys[i];
    unsigned int kmin = g_keymin;
    if (key >= kmin && key != 0u) {
        unsigned int pos = atomicAdd(&g_ccount, 1u);
        if (pos < NCAND) {
            // desc by key, ties asc by index -> pack (key, ~idx), sort desc
            g_cand[pos] = ((unsigned long long)key << 32) |
                          (unsigned long long)(0xFFFFFFFFu - (unsigned int)i);
        }
    }
}

// ---------------- K4: bitonic sort 4096 (descending), emit top 1024 ----------------
__global__ void k_sort() {
    __shared__ unsigned long long s[NCAND];
    int t = threadIdx.x;
    unsigned int C = g_ccount;
    if (C > NCAND) C = NCAND;
    for (int i = t; i < NCAND; i += 1024)
        s[i] = (i < (int)C) ? g_cand[i] : 0ull;
    __syncthreads();

    for (int k = 2; k <= NCAND; k <<= 1) {
        for (int j = k >> 1; j > 0; j >>= 1) {
            for (int i = t; i < NCAND; i += 1024) {
                int ixj = i ^ j;
                if (ixj > i) {
                    unsigned long long x = s[i], y = s[ixj];
                    bool descSeg = ((i & k) == 0);
                    if (descSeg ? (x < y) : (x > y)) { s[i] = y; s[ixj] = x; }
                }
            }
            __syncthreads();
        }
    }

    unsigned long long e = s[t];
    g_sel_key[t] = (unsigned int)(e >> 32);
    g_sel_idx[t] = 0xFFFFFFFFu - (unsigned int)(e & 0xFFFFFFFFu);
}

// ---------------- K5: decode boxes/kps for the 1000 winners ----------------
__global__ void k_decode(const float* __restrict__ b8,  const float* __restrict__ k8,
                         const float* __restrict__ b16, const float* __restrict__ k16,
                         const float* __restrict__ b32, const float* __restrict__ k32) {
    int t = threadIdx.x;
    if (t >= TOPK) return;
    unsigned int key = g_sel_key[t];
    if (key == 0u) {
        g_val[t] = 0;
        g_sc[t] = 0.0f;
        for (int c = 0; c < 4; c++)  g_bx[t * 4 + c] = 0.0f;
        for (int c = 0; c < 10; c++) g_kp[t * 10 + c] = 0.0f;
        return;
    }
    int idx = (int)g_sel_idx[t];
    int li, fw;
    float stride;
    const float* bb;
    const float* kp;
    if (idx < N8)            { li = idx;             stride = 8.0f;  fw = FW8;  bb = b8;  kp = k8;  }
    else if (idx < N8 + N16) { li = idx - N8;        stride = 16.0f; fw = FW16; bb = b16; kp = k16; }
    else                     { li = idx - N8 - N16;  stride = 32.0f; fw = FW32; bb = b32; kp = k32; }

    float cx = (float)(li % fw) * stride;
    float cy = (float)(li / fw) * stride;

    const float* d = bb + (size_t)li * 4;
    g_bx[t * 4 + 0] = cx - d[0] * stride;
    g_bx[t * 4 + 1] = cy - d[1] * stride;
    g_bx[t * 4 + 2] = cx + d[2] * stride;
    g_bx[t * 4 + 3] = cy + d[3] * stride;

    const float* kk = kp + (size_t)li * 10;
    #pragma unroll
    for (int j = 0; j < 5; j++) {
        g_kp[t * 10 + 2 * j]     = kk[2 * j]     * stride + cx;
        g_kp[t * 10 + 2 * j + 1] = kk[2 * j + 1] * stride + cy;
    }
    g_sc[t] = __uint_as_float(key);
    g_val[t] = 1;
}

// ---------------- K6: greedy sequential NMS + write outputs ----------------
__global__ void k_nms(float* __restrict__ out) {
    __shared__ float sx1[TOPK], sy1[TOPK], sx2[TOPK], sy2[TOPK], sar[TOPK];
    __shared__ int skeep[TOPK];
    int t = threadIdx.x;

    if (t < TOPK) {
        float x1 = g_bx[t * 4 + 0], y1 = g_bx[t * 4 + 1];
        float x2 = g_bx[t * 4 + 2], y2 = g_bx[t * 4 + 3];
        sx1[t] = x1; sy1[t] = y1; sx2[t] = x2; sy2[t] = y2;
        sar[t] = (x2 - x1) * (y2 - y1);
        skeep[t] = g_val[t];
    }
    __syncthreads();

    for (int i = 0; i < TOPK; i++) {
        if (skeep[i]) {  // uniform across block
            if (t > i && t < TOPK && skeep[t]) {
                float ltx = fmaxf(sx1[i], sx1[t]);
                float lty = fmaxf(sy1[i], sy1[t]);
                float rbx = fminf(sx2[i], sx2[t]);
                float rby = fminf(sy2[i], sy2[t]);
                float w = fmaxf(rbx - ltx, 0.0f);
                float h = fmaxf(rby - lty, 0.0f);
                float inter = w * h;
                float uni = fmaxf(sar[i] + sar[t] - inter, 1e-9f);
                if (inter / uni > NMS_T) skeep[t] = 0;
            }
        }
        __syncthreads();
    }

    // outputs: [boxes 1000*4 | scores 1000 | kpss 1000*10] = 15000 floats
    if (t < TOPK) {
        int k = skeep[t];
        float m = k ? 1.0f : 0.0f;
        out[t * 4 + 0] = m * g_bx[t * 4 + 0];
        out[t * 4 + 1] = m * g_bx[t * 4 + 1];
        out[t * 4 + 2] = m * g_bx[t * 4 + 2];
        out[t * 4 + 3] = m * g_bx[t * 4 + 3];
        out[4000 + t] = m * g_sc[t];
        #pragma unroll
        for (int c = 0; c < 10; c++)
            out[5000 + t * 10 + c] = m * g_kp[t * 10 + c];
    }
}

// ---------------- launcher ----------------
extern "C" void kernel_launch(void* const* d_in, const int* in_sizes, int n_in,
                              void* d_out, int out_size) {
    // metadata order: x, scores8, bbox8, kps8, scores16, bbox16, kps16, scores32, bbox32, kps32
    const float* s8  = (const float*)d_in[1];
    const float* b8  = (const float*)d_in[2];
    const float* k8  = (const float*)d_in[3];
    const float* s16 = (const float*)d_in[4];
    const float* b16 = (const float*)d_in[5];
    const float* k16 = (const float*)d_in[6];
    const float* s32 = (const float*)d_in[7];
    const float* b32 = (const float*)d_in[8];
    const float* k32 = (const float*)d_in[9];
    float* out = (float*)d_out;

    const int threads = 256;
    const int blocks = (NT + threads - 1) / threads;

    k_zero<<<(NBINS + 1023) / 1024, 1024>>>();
    k_keys<<<blocks, threads>>>(s8, s16, s32);
    k_select<<<1, 1024>>>();
    k_collect<<<blocks, threads>>>();
    k_sort<<<1, 1024>>>();
    k_decode<<<1, 1024>>>(b8, k8, b16, k16, b32, k32);
    k_nms<<<1, 1024>>>(out);
}

// round 3
// speedup vs baseline: 2.7856x; 2.7856x over previous
#include <cuda_runtime.h>
#include <math.h>

// ---------------- problem constants ----------------
#define N8   130560   // (2176/8)*(3840/8)
#define N16  32640    // (2176/16)*(3840/16)
#define N32  8160     // (2176/32)*(3840/32)
#define NT   (N8 + N16 + N32)   // 171360
#define FW8  480
#define FW16 240
#define FW32 120
#define TOPK 1000
#define NCAND 4096
#define NBINS 4096
#define NMS_T 0.4f

// ---------------- device scratch (no allocations allowed) ----------------
__device__ unsigned int        g_keys[NT];
__device__ unsigned int        g_hist[NBINS];
__device__ unsigned int        g_keymin;
__device__ unsigned int        g_ccount;
__device__ unsigned long long  g_cand[NCAND];
__device__ float               g_bx[1024 * 4];
__device__ float               g_sc[1024];
__device__ float               g_kp[1024 * 10];
__device__ int                 g_val[1024];
__device__ unsigned int        g_mask[1024 * 32];   // suppression bitmask rows

// ---------------- K0: zero scratch (runs every graph replay) ----------------
__global__ void k_zero() {
    int i = blockIdx.x * blockDim.x + threadIdx.x;
    if (i < NBINS) g_hist[i] = 0;
    if (i == 0) g_ccount = 0;
}

// ---------------- K1: sigmoid -> key + histogram ----------------
// valid (sigmoid > 0.5) keys lie in (0x3F000000, 0x3F800000]; bin = mantissa[22:11]
__global__ void k_keys(const float* __restrict__ s8,
                       const float* __restrict__ s16,
                       const float* __restrict__ s32) {
    int i = blockIdx.x * blockDim.x + threadIdx.x;
    if (i >= NT) return;
    float raw;
    if (i < N8)            raw = s8[i];
    else if (i < N8 + N16) raw = s16[i - N8];
    else                   raw = s32[i - N8 - N16];
    float sg = 1.0f / (1.0f + expf(-raw));
    unsigned int key = 0u;
    if (sg > 0.5f) key = __float_as_uint(sg);
    g_keys[i] = key;
    if (key) {
        unsigned int off = key - 0x3F000000u;
        unsigned int bin = off >> 11;
        if (bin > NBINS - 1) bin = NBINS - 1;
        atomicAdd(&g_hist[bin], 1u);
    }
}

// ---------------- K2: key threshold so candidate count >= TOPK ----------------
__global__ void k_select() {
    __shared__ unsigned int sh[NBINS];
    __shared__ unsigned int a[1024];
    int t = threadIdx.x;

    for (int i = t; i < NBINS; i += 1024) sh[i] = g_hist[i];
    __syncthreads();

    unsigned int p = sh[t * 4] + sh[t * 4 + 1] + sh[t * 4 + 2] + sh[t * 4 + 3];
    a[t] = p;
    __syncthreads();

    for (int d = 1; d < 1024; d <<= 1) {
        unsigned int v = a[t] + ((t + d < 1024) ? a[t + d] : 0u);
        __syncthreads();
        a[t] = v;
        __syncthreads();
    }

    unsigned int nxt = (t < 1023) ? a[t + 1] : 0u;
    if (a[t] >= TOPK && nxt < TOPK) {
        unsigned int running = nxt;
        int B = t * 4;
        for (int b = t * 4 + 3; b >= t * 4; b--) {
            running += sh[b];
            if (running >= TOPK) { B = b; break; }
        }
        g_keymin = 0x3F000000u + ((unsigned int)B << 11);
    }
    if (t == 0 && a[0] < TOPK) g_keymin = 0x3F000000u;
}

// ---------------- K3: collect candidates ----------------
__global__ void k_collect() {
    int i = blockIdx.x * blockDim.x + threadIdx.x;
    if (i >= NT) return;
    unsigned int key = g_keys[i];
    unsigned int kmin = g_keymin;
    if (key >= kmin && key != 0u) {
        unsigned int pos = atomicAdd(&g_ccount, 1u);
        if (pos < NCAND) {
            // desc by key, ties asc by index -> pack (key, ~idx), sort desc
            g_cand[pos] = ((unsigned long long)key << 32) |
                          (unsigned long long)(0xFFFFFFFFu - (unsigned int)i);
        }
    }
}

// ---------------- K4: bitonic sort 4096 desc + decode winners ----------------
__global__ void k_sortdec(const float* __restrict__ b8,  const float* __restrict__ k8,
                          const float* __restrict__ b16, const float* __restrict__ k16,
                          const float* __restrict__ b32, const float* __restrict__ k32) {
    __shared__ unsigned long long s[NCAND];
    int t = threadIdx.x;
    unsigned int C = g_ccount;
    if (C > NCAND) C = NCAND;
    for (int i = t; i < NCAND; i += 1024)
        s[i] = (i < (int)C) ? g_cand[i] : 0ull;
    __syncthreads();

    for (int k = 2; k <= NCAND; k <<= 1) {
        for (int j = k >> 1; j > 0; j >>= 1) {
            for (int i = t; i < NCAND; i += 1024) {
                int ixj = i ^ j;
                if (ixj > i) {
                    unsigned long long x = s[i], y = s[ixj];
                    bool descSeg = ((i & k) == 0);
                    if (descSeg ? (x < y) : (x > y)) { s[i] = y; s[ixj] = x; }
                }
            }
            __syncthreads();
        }
    }

    // decode the top TOPK directly
    if (t < TOPK) {
        unsigned long long e = s[t];
        unsigned int key = (unsigned int)(e >> 32);
        if (key == 0u) {
            g_val[t] = 0;
            g_sc[t] = 0.0f;
            #pragma unroll
            for (int c = 0; c < 4; c++)  g_bx[t * 4 + c] = 0.0f;
            #pragma unroll
            for (int c = 0; c < 10; c++) g_kp[t * 10 + c] = 0.0f;
        } else {
            int idx = (int)(0xFFFFFFFFu - (unsigned int)(e & 0xFFFFFFFFu));
            int li, fw;
            float stride;
            const float* bb;
            const float* kp;
            if (idx < N8)            { li = idx;            stride = 8.0f;  fw = FW8;  bb = b8;  kp = k8;  }
            else if (idx < N8 + N16) { li = idx - N8;       stride = 16.0f; fw = FW16; bb = b16; kp = k16; }
            else                     { li = idx - N8 - N16; stride = 32.0f; fw = FW32; bb = b32; kp = k32; }

            float cx = (float)(li % fw) * stride;
            float cy = (float)(li / fw) * stride;

            const float* d = bb + (size_t)li * 4;
            g_bx[t * 4 + 0] = cx - d[0] * stride;
            g_bx[t * 4 + 1] = cy - d[1] * stride;
            g_bx[t * 4 + 2] = cx + d[2] * stride;
            g_bx[t * 4 + 3] = cy + d[3] * stride;

            const float* kk = kp + (size_t)li * 10;
            #pragma unroll
            for (int j = 0; j < 5; j++) {
                g_kp[t * 10 + 2 * j]     = kk[2 * j]     * stride + cx;
                g_kp[t * 10 + 2 * j + 1] = kk[2 * j + 1] * stride + cy;
            }
            g_sc[t] = __uint_as_float(key);
            g_val[t] = 1;
        }
    }
}

// ---------------- K5: parallel IoU suppression bitmask ----------------
// row i suppresses column j when j > i and IoU > NMS_T
__global__ void k_mask() {
    int i = blockIdx.x;          // 0..TOPK-1
    int j = threadIdx.x;         // 0..1023
    float ix1 = g_bx[i * 4 + 0], iy1 = g_bx[i * 4 + 1];
    float ix2 = g_bx[i * 4 + 2], iy2 = g_bx[i * 4 + 3];
    float iar = (ix2 - ix1) * (iy2 - iy1);
    bool bit = false;
    if (j < TOPK && j > i) {
        float jx1 = g_bx[j * 4 + 0], jy1 = g_bx[j * 4 + 1];
        float jx2 = g_bx[j * 4 + 2], jy2 = g_bx[j * 4 + 3];
        float jar = (jx2 - jx1) * (jy2 - jy1);
        float w = fmaxf(fminf(ix2, jx2) - fmaxf(ix1, jx1), 0.0f);
        float h = fmaxf(fminf(iy2, jy2) - fmaxf(iy1, jy1), 0.0f);
        float inter = w * h;
        float uni = fmaxf(iar + jar - inter, 1e-9f);
        bit = inter > NMS_T * uni;
    }
    unsigned int b = __ballot_sync(0xFFFFFFFFu, bit);
    if ((j & 31) == 0) g_mask[i * 32 + (j >> 5)] = b;
}

// ---------------- K6: greedy bit-reduce (1 warp) + write outputs ----------------
#define PROC_CHUNK(MARR, CC)                                                     \
    {                                                                            \
        unsigned int vb = svalid[(CC)];                                          \
        unsigned int myrem = rem;                                                \
        unsigned int kb = 0;                                                     \
        _Pragma("unroll")                                                        \
        for (int kk2 = 0; kk2 < 32; kk2++) {                                     \
            unsigned int kept = ((vb >> kk2) & 1u) & ((~(myrem >> kk2)) & 1u);   \
            kb |= kept << kk2;                                                   \
            myrem |= (0u - kept) & MARR[kk2];                                    \
        }                                                                        \
        unsigned int keptbits = __shfl_sync(0xFFFFFFFFu, kb, (CC));              \
        _Pragma("unroll")                                                        \
        for (int kk2 = 0; kk2 < 32; kk2++) {                                     \
            rem |= (0u - ((keptbits >> kk2) & 1u)) & MARR[kk2];                  \
        }                                                                        \
    }

__global__ void k_reduce(float* __restrict__ out) {
    __shared__ unsigned int svalid[32];
    __shared__ unsigned int srem[32];
    int t = threadIdx.x;
    int lane = t & 31;
    int w = t >> 5;

    // pack validity bits: svalid[c] bit k = g_val[c*32+k]
    for (int c = w; c < 32; c += 4) {
        int idx = c * 32 + lane;
        int v = (idx < TOPK) ? g_val[idx] : 0;
        unsigned int b = __ballot_sync(0xFFFFFFFFu, v != 0);
        if (lane == 0) svalid[c] = b;
    }
    __syncthreads();

    if (t < 32) {
        // lane owns suppression word `lane`; 32 chunks of 32 rows, double-buffered
        unsigned int rem = 0;
        unsigned int mA[32], mB[32];
        #pragma unroll
        for (int k = 0; k < 32; k++) mA[k] = g_mask[k * 32 + lane];

        for (int c = 0; c < 32; c += 2) {
            if (c + 1 < 32) {
                #pragma unroll
                for (int k = 0; k < 32; k++) mB[k] = g_mask[((c + 1) * 32 + k) * 32 + lane];
            }
            PROC_CHUNK(mA, c)
            if (c + 2 < 32) {
                #pragma unroll
                for (int k = 0; k < 32; k++) mA[k] = g_mask[((c + 2) * 32 + k) * 32 + lane];
            }
            if (c + 1 < 32) PROC_CHUNK(mB, c + 1)
        }
        srem[lane] = rem;
    }
    __syncthreads();

    // outputs: [boxes 1000*4 | scores 1000 | kpss 1000*10] = 15000 floats
    for (int r = t; r < TOPK; r += 128) {
        unsigned int rw = srem[r >> 5];
        int keep = g_val[r] && !((rw >> (r & 31)) & 1u);
        float m = keep ? 1.0f : 0.0f;
        out[r * 4 + 0] = m * g_bx[r * 4 + 0];
        out[r * 4 + 1] = m * g_bx[r * 4 + 1];
        out[r * 4 + 2] = m * g_bx[r * 4 + 2];
        out[r * 4 + 3] = m * g_bx[r * 4 + 3];
        out[4000 + r] = m * g_sc[r];
        #pragma unroll
        for (int c = 0; c < 10; c++)
            out[5000 + r * 10 + c] = m * g_kp[r * 10 + c];
    }
}

// ---------------- launcher ----------------
extern "C" void kernel_launch(void* const* d_in, const int* in_sizes, int n_in,
                              void* d_out, int out_size) {
    // metadata order: x, scores8, bbox8, kps8, scores16, bbox16, kps16, scores32, bbox32, kps32
    const float* s8  = (const float*)d_in[1];
    const float* b8  = (const float*)d_in[2];
    const float* k8  = (const float*)d_in[3];
    const float* s16 = (const float*)d_in[4];
    const float* b16 = (const float*)d_in[5];
    const float* k16 = (const float*)d_in[6];
    const float* s32 = (const float*)d_in[7];
    const float* b32 = (const float*)d_in[8];
    const float* k32 = (const float*)d_in[9];
    float* out = (float*)d_out;

    const int threads = 256;
    const int blocks = (NT + threads - 1) / threads;

    k_zero<<<(NBINS + 1023) / 1024, 1024>>>();
    k_keys<<<blocks, threads>>>(s8, s16, s32);
    k_select<<<1, 1024>>>();
    k_collect<<<blocks, threads>>>();
    k_sortdec<<<1, 1024>>>(b8, k8, b16, k16, b32, k32);
    k_mask<<<TOPK, 1024>>>();
    k_reduce<<<1, 128>>>(out);
}

// round 5
// speedup vs baseline: 5.6258x; 2.0196x over previous
#include <cuda_runtime.h>
#include <math.h>

// ---------------- problem constants ----------------
#define N8   130560   // (2176/8)*(3840/8)
#define N16  32640
#define N32  8160
#define NT   (N8 + N16 + N32)   // 171360
#define FW8  480
#define FW16 240
#define FW32 120
#define TOPK 1000
#define NCAND 4096
#define NBINS 4096
#define NMS_T 0.4f

#define GRID 148
#define BLK  256
#define NTHREADS (GRID * BLK)      // 37888
#define NWARPS   (NTHREADS / 32)   // 1184

// ---------------- device scratch (no allocations allowed) ----------------
__device__ unsigned int        g_keys[NT];
__device__ unsigned int        g_hist[NBINS];          // zero at entry; re-zeroed each run
__device__ unsigned int        g_keymin;
__device__ unsigned int        g_ccount;               // zero at entry; reset each run
__device__ unsigned long long  g_cand[NCAND];
__device__ unsigned long long  g_sel[1024];
__device__ float               g_bx[1024 * 4];
__device__ float               g_sc[1024];
__device__ float               g_kp[1024 * 10];
__device__ int                 g_val[1024];
__device__ unsigned int        g_mask[1024 * 32];
// software grid barrier (generation-based; survives graph replays)
__device__ unsigned int           g_bar_count;
__device__ volatile unsigned int  g_bar_gen;

__device__ __forceinline__ void grid_sync() {
    __syncthreads();
    if (threadIdx.x == 0) {
        __threadfence();
        unsigned int gen = g_bar_gen;
        if (atomicAdd(&g_bar_count, 1u) == GRID - 1) {
            g_bar_count = 0;
            __threadfence();
            g_bar_gen = gen + 1;
        } else {
            while (g_bar_gen == gen) { }
        }
        __threadfence();
    }
    __syncthreads();
}

__global__ __launch_bounds__(BLK)
void k_all(const float* __restrict__ s8,  const float* __restrict__ b8,  const float* __restrict__ k8,
           const float* __restrict__ s16, const float* __restrict__ b16, const float* __restrict__ k16,
           const float* __restrict__ s32, const float* __restrict__ b32, const float* __restrict__ k32,
           float* __restrict__ out) {
    const int tid  = blockIdx.x * BLK + threadIdx.x;
    const int t    = threadIdx.x;
    const int lane = t & 31;

    // ---------- Phase A: sigmoid -> key, histogram ----------
    // valid keys (sigmoid > 0.5) lie in (0x3F000000, 0x3F800000]; bin = mantissa[22:11]
    for (int i = tid; i < NT; i += NTHREADS) {
        float raw;
        if (i < N8)            raw = s8[i];
        else if (i < N8 + N16) raw = s16[i - N8];
        else                   raw = s32[i - N8 - N16];
        float sg = 1.0f / (1.0f + expf(-raw));
        unsigned int key = 0u;
        if (sg > 0.5f) key = __float_as_uint(sg);
        g_keys[i] = key;
        if (key) {
            unsigned int bin = (key - 0x3F000000u) >> 11;
            if (bin > NBINS - 1) bin = NBINS - 1;
            atomicAdd(&g_hist[bin], 1u);
        }
    }
    grid_sync();

    // ---------- Phase B: threshold bin so candidate count >= TOPK ----------
    if (blockIdx.x == 0) {
        __shared__ unsigned int a[BLK];
        unsigned int loc[16];
        unsigned int p = 0;
        #pragma unroll
        for (int b = 0; b < 16; b++) { loc[b] = g_hist[t * 16 + b]; p += loc[b]; }
        a[t] = p;
        __syncthreads();
        for (int d = 1; d < BLK; d <<= 1) {
            unsigned int v = a[t] + ((t + d < BLK) ? a[t + d] : 0u);
            __syncthreads();
            a[t] = v;
            __syncthreads();
        }
        unsigned int nxt = (t < BLK - 1) ? a[t + 1] : 0u;
        if (a[t] >= TOPK && nxt < TOPK) {
            unsigned int running = nxt;
            int B = t * 16;
            #pragma unroll
            for (int b = 15; b >= 0; b--) {
                running += loc[b];
                if (running >= TOPK) { B = t * 16 + b; break; }
            }
            g_keymin = 0x3F000000u + ((unsigned int)B << 11);
        }
        if (t == 0 && a[0] < TOPK) g_keymin = 0x3F000000u;
    }
    grid_sync();

    // ---------- Phase C: collect candidates; re-zero histogram for next replay ----------
    {
        unsigned int kmin = g_keymin;
        for (int i = tid; i < NT; i += NTHREADS) {
            unsigned int key = g_keys[i];
            if (key >= kmin && key != 0u) {
                unsigned int pos = atomicAdd(&g_ccount, 1u);
                if (pos < NCAND) {
                    // desc by key, ties asc by index -> pack (key, ~idx), larger = better
                    g_cand[pos] = ((unsigned long long)key << 32) |
                                  (unsigned long long)(0xFFFFFFFFu - (unsigned int)i);
                }
            }
        }
        for (int i = tid; i < NBINS; i += NTHREADS) g_hist[i] = 0;
    }
    grid_sync();

    // ---------- Phase D: enumeration rank-sort (exact; packed keys unique) ----------
    {
        unsigned int C = g_ccount;
        if (C > NCAND) C = NCAND;
        if (tid < (int)C) {
            unsigned long long mine = g_cand[tid];
            int rank = 0;
            unsigned int i = 0;
            for (; i + 4 <= C; i += 4) {
                rank += (g_cand[i]     > mine);
                rank += (g_cand[i + 1] > mine);
                rank += (g_cand[i + 2] > mine);
                rank += (g_cand[i + 3] > mine);
            }
            for (; i < C; i++) rank += (g_cand[i] > mine);
            if (rank < TOPK) g_sel[rank] = mine;
        }
    }
    grid_sync();

    // ---------- Phase E: decode the winners ----------
    if (tid < 1024) {
        unsigned int C = g_ccount;
        if (C > NCAND) C = NCAND;
        if (tid < TOPK) {
            if (tid < (int)C) {
                unsigned long long e = g_sel[tid];
                unsigned int key = (unsigned int)(e >> 32);
                int idx = (int)(0xFFFFFFFFu - (unsigned int)(e & 0xFFFFFFFFu));
                int li, fw;
                float stride;
                const float* bb;
                const float* kp;
                if (idx < N8)            { li = idx;            stride = 8.0f;  fw = FW8;  bb = b8;  kp = k8;  }
                else if (idx < N8 + N16) { li = idx - N8;       stride = 16.0f; fw = FW16; bb = b16; kp = k16; }
                else                     { li = idx - N8 - N16; stride = 32.0f; fw = FW32; bb = b32; kp = k32; }
                float cx = (float)(li % fw) * stride;
                float cy = (float)(li / fw) * stride;
                const float* d = bb + (size_t)li * 4;
                g_bx[tid * 4 + 0] = cx - d[0] * stride;
                g_bx[tid * 4 + 1] = cy - d[1] * stride;
                g_bx[tid * 4 + 2] = cx + d[2] * stride;
                g_bx[tid * 4 + 3] = cy + d[3] * stride;
                const float* kk = kp + (size_t)li * 10;
                #pragma unroll
                for (int j = 0; j < 5; j++) {
                    g_kp[tid * 10 + 2 * j]     = kk[2 * j]     * stride + cx;
                    g_kp[tid * 10 + 2 * j + 1] = kk[2 * j + 1] * stride + cy;
                }
                g_sc[tid] = __uint_as_float(key);
                g_val[tid] = 1;
            } else {
                g_val[tid] = 0;
                g_sc[tid] = 0.0f;
                #pragma unroll
                for (int c = 0; c < 4; c++)  g_bx[tid * 4 + c] = 0.0f;
                #pragma unroll
                for (int c = 0; c < 10; c++) g_kp[tid * 10 + c] = 0.0f;
            }
        } else {
            // rows 1000..1023: zero boxes so stray IoU bits can't appear
            #pragma unroll
            for (int c = 0; c < 4; c++) g_bx[tid * 4 + c] = 0.0f;
        }
    }
    grid_sync();

    // ---------- Phase F: IoU suppression bitmask (32000 warp-tasks) ----------
    if (tid == 0) g_ccount = 0;   // reset for next replay (consumed already)
    {
        int gw = tid >> 5;
        for (int task = gw; task < TOPK * 32; task += NWARPS) {
            int i  = task >> 5;
            int wj = task & 31;
            int j  = wj * 32 + lane;
            float ix1 = g_bx[i * 4 + 0], iy1 = g_bx[i * 4 + 1];
            float ix2 = g_bx[i * 4 + 2], iy2 = g_bx[i * 4 + 3];
            float iar = (ix2 - ix1) * (iy2 - iy1);
            bool bit = false;
            if (j < TOPK && j > i) {
                float jx1 = g_bx[j * 4 + 0], jy1 = g_bx[j * 4 + 1];
                float jx2 = g_bx[j * 4 + 2], jy2 = g_bx[j * 4 + 3];
                float jar = (jx2 - jx1) * (jy2 - jy1);
                float w = fmaxf(fminf(ix2, jx2) - fmaxf(ix1, jx1), 0.0f);
                float h = fmaxf(fminf(iy2, jy2) - fmaxf(iy1, jy1), 0.0f);
                float inter = w * h;
                float uni = fmaxf(iar + jar - inter, 1e-9f);
                bit = inter > NMS_T * uni;
            }
            unsigned int b = __ballot_sync(0xFFFFFFFFu, bit);
            if (lane == 0) g_mask[i * 32 + wj] = b;
        }
    }
    grid_sync();

    // ---------- Phase G: greedy bit-reduce (1 warp) + outputs ----------
    if (blockIdx.x == 0) {
        __shared__ unsigned int svalid[32];
        __shared__ unsigned int srem[32];
        int w = t >> 5;   // 8 warps
        for (int c = w; c < 32; c += 8) {
            int idx = c * 32 + lane;
            int v = (idx < TOPK) ? g_val[idx] : 0;
            unsigned int b = __ballot_sync(0xFFFFFFFFu, v != 0);
            if (lane == 0) svalid[c] = b;
        }
        __syncthreads();

        if (t < 32) {
            unsigned int rem = 0;
            unsigned int mA[32], mB[32];
            #pragma unroll
            for (int k = 0; k < 32; k++) mA[k] = g_mask[k * 32 + lane];

            for (int c = 0; c < 32; c += 2) {
                #pragma unroll
                for (int k = 0; k < 32; k++) mB[k] = g_mask[((c + 1) * 32 + k) * 32 + lane];
                {   // process chunk c with mA
                    unsigned int vb = svalid[c];
                    unsigned int myrem = rem;
                    unsigned int kb = 0;
                    #pragma unroll
                    for (int k2 = 0; k2 < 32; k2++) {
                        unsigned int kept = ((vb >> k2) & 1u) & ((~(myrem >> k2)) & 1u);
                        kb |= kept << k2;
                        myrem |= (0u - kept) & mA[k2];
                    }
                    unsigned int keptbits = __shfl_sync(0xFFFFFFFFu, kb, c);
                    #pragma unroll
                    for (int k2 = 0; k2 < 32; k2++)
                        rem |= (0u - ((keptbits >> k2) & 1u)) & mA[k2];
                }
                if (c + 2 < 32) {
                    #pragma unroll
                    for (int k = 0; k < 32; k++) mA[k] = g_mask[((c + 2) * 32 + k) * 32 + lane];
                }
                {   // process chunk c+1 with mB
                    unsigned int vb = svalid[c + 1];
                    unsigned int myrem = rem;
                    unsigned int kb = 0;
                    #pragma unroll
                    for (int k2 = 0; k2 < 32; k2++) {
                        unsigned int kept = ((vb >> k2) & 1u) & ((~(myrem >> k2)) & 1u);
                        kb |= kept << k2;
                        myrem |= (0u - kept) & mB[k2];
                    }
                    unsigned int keptbits = __shfl_sync(0xFFFFFFFFu, kb, c + 1);
                    #pragma unroll
                    for (int k2 = 0; k2 < 32; k2++)
                        rem |= (0u - ((keptbits >> k2) & 1u)) & mB[k2];
                }
            }
            srem[lane] = rem;
        }
        __syncthreads();

        // outputs: [boxes 1000*4 | scores 1000 | kpss 1000*10] = 15000 floats
        for (int r = t; r < TOPK; r += BLK) {
            unsigned int rw = srem[r >> 5];
            int keep = g_val[r] && !((rw >> (r & 31)) & 1u);
            float m = keep ? 1.0f : 0.0f;
            out[r * 4 + 0] = m * g_bx[r * 4 + 0];
            out[r * 4 + 1] = m * g_bx[r * 4 + 1];
            out[r * 4 + 2] = m * g_bx[r * 4 + 2];
            out[r * 4 + 3] = m * g_bx[r * 4 + 3];
            out[4000 + r] = m * g_sc[r];
            #pragma unroll
            for (int c = 0; c < 10; c++)
                out[5000 + r * 10 + c] = m * g_kp[r * 10 + c];
        }
    }
}

// ---------------- launcher: ONE persistent kernel ----------------
extern "C" void kernel_launch(void* const* d_in, const int* in_sizes, int n_in,
                              void* d_out, int out_size) {
    // metadata order: x, scores8, bbox8, kps8, scores16, bbox16, kps16, scores32, bbox32, kps32
    const float* s8  = (const float*)d_in[1];
    const float* b8  = (const float*)d_in[2];
    const float* k8  = (const float*)d_in[3];
    const float* s16 = (const float*)d_in[4];
    const float* b16 = (const float*)d_in[5];
    const float* k16 = (const float*)d_in[6];
    const float* s32 = (const float*)d_in[7];
    const float* b32 = (const float*)d_in[8];
    const float* k32 = (const float*)d_in[9];
    float* out = (float*)d_out;

    k_all<<<GRID, BLK>>>(s8, b8, k8, s16, b16, k16, s32, b32, k32, out);
}